// round 3
// baseline (speedup 1.0000x reference)
#include <cuda_runtime.h>
#include <cstdint>

// ---------------------------------------------------------------------------
// GCN: out = softmax(relu(agg(relu(agg(relu(agg(X@W1))@W2))@W3)))
// using linearity: agg(X) @ W == agg(X @ W)  (GEMM first, then SpMM).
// CSR built per call. Scratch in __device__ globals referenced by symbol.
// edge_index dtype (int32 vs int64) detected on-device once per call.
// ---------------------------------------------------------------------------

#define NMAX 50000
#define EMAX 800000

__device__ int   g_is64;
__device__ int   g_deg[NMAX];
__device__ int   g_cnt[NMAX];
__device__ int   g_rowstart[NMAX + 1];
__device__ int   g_col[EMAX];
__device__ float g_w[EMAX];
__device__ float g_dinv[NMAX];
__device__ float g_bufA[(size_t)NMAX * 128];
__device__ float g_bufB[(size_t)NMAX * 128];

// ---------------------------------------------------------------- dtype probe
// Sample 256 values from the src half interpreted as int64. Safe in both
// layouts: indices < E int64-slots == 2E int32 elements. If ALL samples are
// in [0, N), the buffer is int64 (high words zero); otherwise int32.
__global__ void detect_dtype_kernel(const void* __restrict__ ei, int E, int N) {
    __shared__ int allok;
    if (threadIdx.x == 0) allok = 1;
    __syncthreads();
    const long long* p = (const long long*)ei;
    int stride = E / 256;
    long long v = p[(size_t)threadIdx.x * stride];
    if (v < 0 || v >= (long long)N) atomicAnd(&allok, 0);
    __syncthreads();
    if (threadIdx.x == 0) g_is64 = allok;
}

__device__ __forceinline__ int edge_at(const void* ei, int E, int which_half, int e) {
    // which_half: 0 = src, 1 = dst
    if (g_is64) return (int)((const long long*)ei)[(size_t)which_half * E + e];
    return ((const int*)ei)[(size_t)which_half * E + e];
}

// ---------------------------------------------------------------- CSR build
__global__ void zero_int2_kernel(int n) {
    int i = blockIdx.x * blockDim.x + threadIdx.x;
    if (i < n) { g_deg[i] = 0; g_cnt[i] = 0; }
}

__global__ void count_deg_kernel(const void* __restrict__ ei, int E) {
    int e = blockIdx.x * blockDim.x + threadIdx.x;
    if (e < E) atomicAdd(&g_deg[edge_at(ei, E, 1, e)], 1);
}

__global__ void dinv_kernel(int n) {
    int i = blockIdx.x * blockDim.x + threadIdx.x;
    if (i < n) {
        int d = g_deg[i];
        float fd = (float)(d > 0 ? d : 1);
        g_dinv[i] = rsqrtf(fd);
    }
}

// single-block exclusive scan over g_deg -> g_rowstart (n up to 50000)
__global__ void scan_kernel(int n) {
    __shared__ int sdata[1024];
    int carry = 0;
    if (threadIdx.x == 0) g_rowstart[0] = 0;
    for (int base = 0; base < n; base += 1024) {
        int i = base + (int)threadIdx.x;
        int v = (i < n) ? g_deg[i] : 0;
        sdata[threadIdx.x] = v;
        __syncthreads();
        #pragma unroll
        for (int off = 1; off < 1024; off <<= 1) {
            int t = (threadIdx.x >= (unsigned)off) ? sdata[threadIdx.x - off] : 0;
            __syncthreads();
            sdata[threadIdx.x] += t;
            __syncthreads();
        }
        if (i < n) g_rowstart[i + 1] = carry + sdata[threadIdx.x];
        carry += sdata[1023];
        __syncthreads();
    }
}

__global__ void scatter_kernel(const void* __restrict__ ei, int E) {
    int e = blockIdx.x * blockDim.x + threadIdx.x;
    if (e >= E) return;
    int s = edge_at(ei, E, 0, e);
    int d = edge_at(ei, E, 1, e);
    int pos = g_rowstart[d] + atomicAdd(&g_cnt[d], 1);
    g_col[pos] = s;
    g_w[pos] = g_dinv[s] * g_dinv[d];
}

// ---------------------------------------------------------------- SGEMM
// C[M, BN] = A[M, 128] @ B[128, BN].  BM=128, BK=16, 256 threads, 8xTN tiles.
enum Buf { BUF_A, BUF_B };
__device__ __forceinline__ float* bufPtr(Buf b) { return b == BUF_A ? g_bufA : g_bufB; }

template <int BN, int TN>
__device__ __forceinline__ void sgemm_body(const float* __restrict__ A,
                                           const float* __restrict__ B,
                                           float* __restrict__ C, int M) {
    constexpr int BM = 128, BK = 16, TM = 8;
    __shared__ float As[BK][BM];
    __shared__ float Bs[BK][BN];

    const int tid = threadIdx.x;
    const int rowBase = blockIdx.x * BM;
    const int ty = tid / 16;  // 0..15
    const int tx = tid % 16;  // 0..15

    float acc[TM][TN];
    #pragma unroll
    for (int i = 0; i < TM; i++)
        #pragma unroll
        for (int j = 0; j < TN; j++) acc[i][j] = 0.0f;

    for (int kc = 0; kc < 128; kc += BK) {
        #pragma unroll
        for (int l = 0; l < 2; l++) {
            int idx = tid + l * 256;
            int r = idx >> 2;
            int c4 = idx & 3;
            float4 v = make_float4(0.f, 0.f, 0.f, 0.f);
            int grow = rowBase + r;
            if (grow < M)
                v = *(const float4*)(A + (size_t)grow * 128 + kc + c4 * 4);
            As[c4 * 4 + 0][r] = v.x;
            As[c4 * 4 + 1][r] = v.y;
            As[c4 * 4 + 2][r] = v.z;
            As[c4 * 4 + 3][r] = v.w;
        }
        constexpr int BLOADS = (BK * BN / 4) / 256;  // 2 for BN=128, 1 for BN=64
        #pragma unroll
        for (int l = 0; l < BLOADS; l++) {
            int idx = tid + l * 256;
            int r = idx / (BN / 4);
            int c4 = idx % (BN / 4);
            float4 v = *(const float4*)(B + (size_t)(kc + r) * BN + c4 * 4);
            *(float4*)&Bs[r][c4 * 4] = v;
        }
        __syncthreads();

        #pragma unroll
        for (int k = 0; k < BK; k++) {
            float rm[TM], rn[TN];
            #pragma unroll
            for (int i = 0; i < TM; i++) rm[i] = As[k][ty * TM + i];
            #pragma unroll
            for (int j = 0; j < TN; j++) rn[j] = Bs[k][tx * TN + j];
            #pragma unroll
            for (int i = 0; i < TM; i++)
                #pragma unroll
                for (int j = 0; j < TN; j++) acc[i][j] += rm[i] * rn[j];
        }
        __syncthreads();
    }

    #pragma unroll
    for (int i = 0; i < TM; i++) {
        int grow = rowBase + ty * TM + i;
        if (grow < M) {
            #pragma unroll
            for (int j = 0; j < TN; j += 4) {
                float4 v = make_float4(acc[i][j], acc[i][j + 1], acc[i][j + 2], acc[i][j + 3]);
                *(float4*)(C + (size_t)grow * BN + tx * TN + j) = v;
            }
        }
    }
}

// A from harness pointer (layer 1), C to device-global buffer
template <int BN, int TN, Buf OUTB>
__global__ __launch_bounds__(256) void sgemm_k128_g(const float* __restrict__ A,
                                                    const float* __restrict__ B, int M) {
    sgemm_body<BN, TN>(A, B, bufPtr(OUTB), M);
}

// A from device-global buffer (layers 2, 3)
template <int BN, int TN, Buf INB, Buf OUTB>
__global__ __launch_bounds__(256) void sgemm_k128_gg(const float* __restrict__ B, int M) {
    sgemm_body<BN, TN>(bufPtr(INB), B, bufPtr(OUTB), M);
}

// ---------------------------------------------------------------- SpMM (CSR)
// warp per node, F=128 floats per row (one float4 per lane), fused relu
template <Buf INB, Buf OUTB>
__global__ __launch_bounds__(256) void agg_relu128_g(int n) {
    const float* Y = bufPtr(INB);
    float* H = bufPtr(OUTB);
    int warpId = (blockIdx.x * blockDim.x + threadIdx.x) >> 5;
    int lane = threadIdx.x & 31;
    if (warpId >= n) return;
    int s = g_rowstart[warpId];
    int e = g_rowstart[warpId + 1];
    float4 acc = make_float4(0.f, 0.f, 0.f, 0.f);
    for (int i = s; i < e; i++) {
        int c = g_col[i];
        float ww = g_w[i];
        float4 v = __ldg((const float4*)(Y + (size_t)c * 128) + lane);
        acc.x += ww * v.x;
        acc.y += ww * v.y;
        acc.z += ww * v.z;
        acc.w += ww * v.w;
    }
    acc.x = fmaxf(acc.x, 0.f);
    acc.y = fmaxf(acc.y, 0.f);
    acc.z = fmaxf(acc.z, 0.f);
    acc.w = fmaxf(acc.w, 0.f);
    ((float4*)(H + (size_t)warpId * 128))[lane] = acc;
}

// warp per node, F=64 (float2 per lane), fused relu + softmax
template <Buf INB>
__global__ __launch_bounds__(256) void agg_softmax64_g(float* __restrict__ out, int n) {
    const float* Y = bufPtr(INB);
    int warpId = (blockIdx.x * blockDim.x + threadIdx.x) >> 5;
    int lane = threadIdx.x & 31;
    if (warpId >= n) return;
    int s = g_rowstart[warpId];
    int e = g_rowstart[warpId + 1];
    float ax = 0.f, ay = 0.f;
    for (int i = s; i < e; i++) {
        int c = g_col[i];
        float ww = g_w[i];
        float2 v = __ldg((const float2*)(Y + (size_t)c * 64) + lane);
        ax += ww * v.x;
        ay += ww * v.y;
    }
    ax = fmaxf(ax, 0.f);
    ay = fmaxf(ay, 0.f);
    float m = fmaxf(ax, ay);
    #pragma unroll
    for (int off = 16; off >= 1; off >>= 1)
        m = fmaxf(m, __shfl_xor_sync(0xffffffffu, m, off));
    float e0 = __expf(ax - m);
    float e1 = __expf(ay - m);
    float ssum = e0 + e1;
    #pragma unroll
    for (int off = 16; off >= 1; off >>= 1)
        ssum += __shfl_xor_sync(0xffffffffu, ssum, off);
    float inv = 1.0f / ssum;
    float2 r = make_float2(e0 * inv, e1 * inv);
    ((float2*)(out + (size_t)warpId * 64))[lane] = r;
}

// ---------------------------------------------------------------- launch
extern "C" void kernel_launch(void* const* d_in, const int* in_sizes, int n_in,
                              void* d_out, int out_size) {
    const float* X = (const float*)d_in[0];
    const void* ei = d_in[1];
    const float* W1 = (const float*)d_in[2];
    const float* W2 = (const float*)d_in[3];
    const float* W3 = (const float*)d_in[4];
    float* out = (float*)d_out;

    const int N = in_sizes[0] / 128;   // 50000
    const int E = in_sizes[1] / 2;     // 800000

    const int T = 256;
    // dtype probe + CSR build
    detect_dtype_kernel<<<1, 256>>>(ei, E, N);
    zero_int2_kernel<<<(N + T - 1) / T, T>>>(N);
    count_deg_kernel<<<(E + T - 1) / T, T>>>(ei, E);
    dinv_kernel<<<(N + T - 1) / T, T>>>(N);
    scan_kernel<<<1, 1024>>>(N);
    scatter_kernel<<<(E + T - 1) / T, T>>>(ei, E);

    const int gemmBlocks = (N + 127) / 128;
    const int aggBlocks = (N * 32 + T - 1) / T;

    // Layer 1: bufA = X @ W1 ; bufB = relu(agg(bufA))
    sgemm_k128_g<128, 8, BUF_A><<<gemmBlocks, 256>>>(X, W1, N);
    agg_relu128_g<BUF_A, BUF_B><<<aggBlocks, T>>>(N);
    // Layer 2: bufA = bufB @ W2 ; bufB = relu(agg(bufA))
    sgemm_k128_gg<128, 8, BUF_B, BUF_A><<<gemmBlocks, 256>>>(W2, N);
    agg_relu128_g<BUF_A, BUF_B><<<aggBlocks, T>>>(N);
    // Layer 3: bufA = bufB @ W3 (F_out=64) ; out = softmax(relu(agg(bufA)))
    sgemm_k128_gg<64, 4, BUF_B, BUF_A><<<gemmBlocks, 256>>>(W3, N);
    agg_softmax64_g<BUF_A><<<aggBlocks, T>>>(out, N);
}

// round 5
// speedup vs baseline: 1.2869x; 1.2869x over previous
#include <cuda_runtime.h>
#include <cstdint>

// ---------------------------------------------------------------------------
// GCN: out = softmax(relu(agg(relu(agg(relu(agg(X@W1))@W2))@W3)))
// agg(X) @ W == agg(X @ W)  -> GEMM first (mma.sync tf32), then CSR SpMM.
// tcgen05 is unavailable (harness targets sm_103, not sm_103a) -> use
// baseline PTX mma.sync.m16n8k8 tf32 (sm_80+ feature, valid here).
// ---------------------------------------------------------------------------

#define NMAX 50000
#define EMAX 800000

__device__ int   g_is64;
__device__ int   g_deg[NMAX];
__device__ int   g_cnt[NMAX];
__device__ int   g_rowstart[NMAX + 1];
__device__ int   g_col[EMAX];
__device__ float g_w[EMAX];
__device__ float g_dinv[NMAX];
__device__ float g_bufA[(size_t)NMAX * 128];
__device__ float g_bufB[(size_t)NMAX * 128];
// W fragment-interleaved, tf32, transposed: wt[j * NDIM + n] = float2(
//   tf32(W[8*(j>>2)+(j&3)][n]), tf32(W[8*(j>>2)+(j&3)+4][n]) ), j in [0,64)
__device__ float2 g_wt1[64 * 128];
__device__ float2 g_wt2[64 * 128];
__device__ float2 g_wt3[64 * 64];

__device__ __forceinline__ uint32_t f2tf32(float f) {
    uint32_t u;
    asm("cvt.rna.tf32.f32 %0, %1;" : "=r"(u) : "f"(f));
    return u;
}

__device__ __forceinline__ void mma_tf32(float* d, uint32_t a0, uint32_t a1,
                                         uint32_t a2, uint32_t a3,
                                         uint32_t b0, uint32_t b1) {
    asm volatile(
        "mma.sync.aligned.m16n8k8.row.col.f32.tf32.tf32.f32 "
        "{%0,%1,%2,%3}, {%4,%5,%6,%7}, {%8,%9}, {%0,%1,%2,%3};"
        : "+f"(d[0]), "+f"(d[1]), "+f"(d[2]), "+f"(d[3])
        : "r"(a0), "r"(a1), "r"(a2), "r"(a3), "r"(b0), "r"(b1));
}

// ---------------------------------------------------------------- dtype probe
__global__ void detect_dtype_kernel(const void* __restrict__ ei, int E, int N) {
    __shared__ int allok;
    if (threadIdx.x == 0) allok = 1;
    __syncthreads();
    const long long* p = (const long long*)ei;
    int stride = E / 256;
    long long v = p[(size_t)threadIdx.x * stride];
    if (v < 0 || v >= (long long)N) atomicAnd(&allok, 0);
    __syncthreads();
    if (threadIdx.x == 0) g_is64 = allok;
}

__device__ __forceinline__ int edge_at(const void* ei, int E, int half, int e) {
    if (g_is64) return (int)((const long long*)ei)[(size_t)half * E + e];
    return ((const int*)ei)[(size_t)half * E + e];
}

// ---------------------------------------------------------------- CSR build
__global__ void zero_int2_kernel(int n) {
    int i = blockIdx.x * blockDim.x + threadIdx.x;
    if (i < n) { g_deg[i] = 0; g_cnt[i] = 0; }
}
__global__ void count_deg_kernel(const void* __restrict__ ei, int E) {
    int e = blockIdx.x * blockDim.x + threadIdx.x;
    if (e < E) atomicAdd(&g_deg[edge_at(ei, E, 1, e)], 1);
}
__global__ void dinv_kernel(int n) {
    int i = blockIdx.x * blockDim.x + threadIdx.x;
    if (i < n) {
        int d = g_deg[i];
        g_dinv[i] = rsqrtf((float)(d > 0 ? d : 1));
    }
}
__global__ void scan_kernel(int n) {
    __shared__ int sdata[1024];
    int carry = 0;
    if (threadIdx.x == 0) g_rowstart[0] = 0;
    for (int base = 0; base < n; base += 1024) {
        int i = base + (int)threadIdx.x;
        int v = (i < n) ? g_deg[i] : 0;
        sdata[threadIdx.x] = v;
        __syncthreads();
        #pragma unroll
        for (int off = 1; off < 1024; off <<= 1) {
            int t = (threadIdx.x >= (unsigned)off) ? sdata[threadIdx.x - off] : 0;
            __syncthreads();
            sdata[threadIdx.x] += t;
            __syncthreads();
        }
        if (i < n) g_rowstart[i + 1] = carry + sdata[threadIdx.x];
        carry += sdata[1023];
        __syncthreads();
    }
}
__global__ void scatter_kernel(const void* __restrict__ ei, int E) {
    int e = blockIdx.x * blockDim.x + threadIdx.x;
    if (e >= E) return;
    int s = edge_at(ei, E, 0, e);
    int d = edge_at(ei, E, 1, e);
    int pos = g_rowstart[d] + atomicAdd(&g_cnt[d], 1);
    g_col[pos] = s;
    g_w[pos] = g_dinv[s] * g_dinv[d];
}

// ---------------------------------------------------------------- buffers
enum Buf { BUF_A, BUF_B };
__device__ __forceinline__ float* bufPtr(Buf b) { return b == BUF_A ? g_bufA : g_bufB; }
__device__ __forceinline__ float2* wtPtr(int w) {
    return w == 1 ? g_wt1 : (w == 2 ? g_wt2 : g_wt3);
}

// W prep: fragment-interleaved tf32 transpose (see g_wt1 comment).
template <int WSEL, int NDIM>
__global__ void prep_w(const float* __restrict__ W) {
    int i = blockIdx.x * blockDim.x + threadIdx.x;   // over 64*NDIM
    if (i >= 64 * NDIM) return;
    int j = i / NDIM;
    int n = i % NDIM;
    int k0 = 8 * (j >> 2) + (j & 3);
    float2 v;
    v.x = __uint_as_float(f2tf32(W[(size_t)k0 * NDIM + n]));
    v.y = __uint_as_float(f2tf32(W[(size_t)(k0 + 4) * NDIM + n]));
    wtPtr(WSEL)[i] = v;
}

// ---------------------------------------------------------------- mma GEMM
// C[M, N_DIM] = A[M,128] @ W[128,N_DIM].  Block = 128 rows, 8 warps x 16 rows.
// B staged in SMEM as Bs[j*(N_DIM+4) + n] (float2); row stride N_DIM+4 makes
// the compute-loop LDS.64 bank-pair = (4*tig + g) mod 16 -> conflict-free.
template <int N_DIM, int WSEL, Buf OUTB, Buf INB, bool EXT>
__global__ __launch_bounds__(256) void gemm_mma(const float* __restrict__ Aext, int M) {
    extern __shared__ float2 Bs[];
    constexpr int NT = N_DIM / 8;
    constexpr int NPAD = N_DIM + 4;

    const int tid = threadIdx.x;
    const float2* wt = wtPtr(WSEL);
    // stage W fragments
    #pragma unroll
    for (int l = 0; l < (64 * N_DIM) / 256; l++) {
        int i = tid + l * 256;
        int j = i / N_DIM;
        int n = i % N_DIM;
        Bs[j * NPAD + n] = wt[i];
    }
    __syncthreads();

    const int wid = tid >> 5;
    const int lane = tid & 31;
    const int g = lane >> 2;
    const int tig = lane & 3;
    const int rowBase = blockIdx.x * 128 + wid * 16;
    const int m0 = rowBase + g;
    const int m1 = m0 + 8;
    const float* A = EXT ? Aext : bufPtr(INB);
    const float* Ar0 = A + (size_t)(m0 < M ? m0 : M - 1) * 128;
    const float* Ar1 = A + (size_t)(m1 < M ? m1 : M - 1) * 128;

    float acc[NT][4];
    #pragma unroll
    for (int nt = 0; nt < NT; nt++) {
        acc[nt][0] = 0.f; acc[nt][1] = 0.f; acc[nt][2] = 0.f; acc[nt][3] = 0.f;
    }

    #pragma unroll 4
    for (int s = 0; s < 16; s++) {
        const int k0 = 8 * s;
        uint32_t a0 = f2tf32(Ar0[k0 + tig]);
        uint32_t a2 = f2tf32(Ar0[k0 + tig + 4]);
        uint32_t a1 = f2tf32(Ar1[k0 + tig]);
        uint32_t a3 = f2tf32(Ar1[k0 + tig + 4]);
        const float2* brow = Bs + (size_t)(s * 4 + tig) * NPAD + g;
        #pragma unroll
        for (int nt = 0; nt < NT; nt++) {
            float2 b = brow[nt * 8];
            mma_tf32(acc[nt], a0, a1, a2, a3,
                     __float_as_uint(b.x), __float_as_uint(b.y));
        }
    }

    float* C = bufPtr(OUTB);
    if (m0 < M) {
        float* dst = C + (size_t)m0 * N_DIM + tig * 2;
        #pragma unroll
        for (int nt = 0; nt < NT; nt++)
            *(float2*)(dst + nt * 8) = make_float2(acc[nt][0], acc[nt][1]);
    }
    if (m1 < M) {
        float* dst = C + (size_t)m1 * N_DIM + tig * 2;
        #pragma unroll
        for (int nt = 0; nt < NT; nt++)
            *(float2*)(dst + nt * 8) = make_float2(acc[nt][2], acc[nt][3]);
    }
}

// ---------------------------------------------------------------- SpMM (CSR)
template <Buf INB, Buf OUTB>
__global__ __launch_bounds__(256) void agg_relu128_g(int n) {
    const float* Y = bufPtr(INB);
    float* H = bufPtr(OUTB);
    int warpId = (blockIdx.x * blockDim.x + threadIdx.x) >> 5;
    int lane = threadIdx.x & 31;
    if (warpId >= n) return;
    int s = g_rowstart[warpId];
    int e = g_rowstart[warpId + 1];
    float4 acc = make_float4(0.f, 0.f, 0.f, 0.f);
    for (int i = s; i < e; i++) {
        int c = g_col[i];
        float ww = g_w[i];
        float4 v = __ldg((const float4*)(Y + (size_t)c * 128) + lane);
        acc.x += ww * v.x;
        acc.y += ww * v.y;
        acc.z += ww * v.z;
        acc.w += ww * v.w;
    }
    acc.x = fmaxf(acc.x, 0.f);
    acc.y = fmaxf(acc.y, 0.f);
    acc.z = fmaxf(acc.z, 0.f);
    acc.w = fmaxf(acc.w, 0.f);
    ((float4*)(H + (size_t)warpId * 128))[lane] = acc;
}

template <Buf INB>
__global__ __launch_bounds__(256) void agg_softmax64_g(float* __restrict__ out, int n) {
    const float* Y = bufPtr(INB);
    int warpId = (blockIdx.x * blockDim.x + threadIdx.x) >> 5;
    int lane = threadIdx.x & 31;
    if (warpId >= n) return;
    int s = g_rowstart[warpId];
    int e = g_rowstart[warpId + 1];
    float ax = 0.f, ay = 0.f;
    for (int i = s; i < e; i++) {
        int c = g_col[i];
        float ww = g_w[i];
        float2 v = __ldg((const float2*)(Y + (size_t)c * 64) + lane);
        ax += ww * v.x;
        ay += ww * v.y;
    }
    ax = fmaxf(ax, 0.f);
    ay = fmaxf(ay, 0.f);
    float m = fmaxf(ax, ay);
    #pragma unroll
    for (int off = 16; off >= 1; off >>= 1)
        m = fmaxf(m, __shfl_xor_sync(0xffffffffu, m, off));
    float e0 = __expf(ax - m);
    float e1 = __expf(ay - m);
    float ssum = e0 + e1;
    #pragma unroll
    for (int off = 16; off >= 1; off >>= 1)
        ssum += __shfl_xor_sync(0xffffffffu, ssum, off);
    float inv = 1.0f / ssum;
    ((float2*)(out + (size_t)warpId * 64))[lane] = make_float2(e0 * inv, e1 * inv);
}

// ---------------------------------------------------------------- launch
extern "C" void kernel_launch(void* const* d_in, const int* in_sizes, int n_in,
                              void* d_out, int out_size) {
    const float* X = (const float*)d_in[0];
    const void* ei = d_in[1];
    const float* W1 = (const float*)d_in[2];
    const float* W2 = (const float*)d_in[3];
    const float* W3 = (const float*)d_in[4];
    float* out = (float*)d_out;

    const int N = in_sizes[0] / 128;   // 50000
    const int E = in_sizes[1] / 2;     // 800000

    const int T = 256;
    detect_dtype_kernel<<<1, 256>>>(ei, E, N);
    zero_int2_kernel<<<(N + T - 1) / T, T>>>(N);
    count_deg_kernel<<<(E + T - 1) / T, T>>>(ei, E);
    dinv_kernel<<<(N + T - 1) / T, T>>>(N);
    scan_kernel<<<1, 1024>>>(N);
    scatter_kernel<<<(E + T - 1) / T, T>>>(ei, E);

    prep_w<1, 128><<<(64 * 128 + T - 1) / T, T>>>(W1);
    prep_w<2, 128><<<(64 * 128 + T - 1) / T, T>>>(W2);
    prep_w<3, 64><<<(64 * 64 + T - 1) / T, T>>>(W3);

    const int gemmBlocks = (N + 127) / 128;
    const int aggBlocks = (N * 32 + T - 1) / T;
    const int SMEM_128 = 64 * (128 + 4) * sizeof(float2);  // 67584
    const int SMEM_64  = 64 * (64 + 4) * sizeof(float2);   // 34816

    auto g1 = gemm_mma<128, 1, BUF_A, BUF_A, true>;
    auto g2 = gemm_mma<128, 2, BUF_A, BUF_B, false>;
    auto g3 = gemm_mma<64, 3, BUF_A, BUF_B, false>;
    cudaFuncSetAttribute(g1, cudaFuncAttributeMaxDynamicSharedMemorySize, SMEM_128);
    cudaFuncSetAttribute(g2, cudaFuncAttributeMaxDynamicSharedMemorySize, SMEM_128);
    cudaFuncSetAttribute(g3, cudaFuncAttributeMaxDynamicSharedMemorySize, SMEM_64);

    // Layer 1: bufA = X @ W1 ; bufB = relu(agg(bufA))
    g1<<<gemmBlocks, 256, SMEM_128>>>(X, N);
    agg_relu128_g<BUF_A, BUF_B><<<aggBlocks, T>>>(N);
    // Layer 2
    g2<<<gemmBlocks, 256, SMEM_128>>>(nullptr, N);
    agg_relu128_g<BUF_A, BUF_B><<<aggBlocks, T>>>(N);
    // Layer 3 (N=64) + fused relu+softmax
    g3<<<gemmBlocks, 256, SMEM_64>>>(nullptr, N);
    agg_softmax64_g<BUF_A><<<aggBlocks, T>>>(out, N);
}

// round 6
// speedup vs baseline: 1.4996x; 1.1653x over previous
#include <cuda_runtime.h>
#include <cuda_fp16.h>
#include <cstdint>

// ---------------------------------------------------------------------------
// GCN: out = softmax(relu(agg(relu(agg(relu(agg(X@W1))@W2))@W3)))
// agg(X) @ W == agg(X @ W)  -> GEMM first (mma.sync tf32), then CSR SpMM.
// GEMM outputs stored fp16 (gather traffic halved); agg accumulates fp32.
// ---------------------------------------------------------------------------

#define NMAX 50000
#define EMAX 800000

__device__ int    g_is64;
__device__ int    g_deg[NMAX];
__device__ int    g_cnt[NMAX];
__device__ int    g_rowstart[NMAX + 1];
__device__ int    g_col[EMAX];
__device__ float  g_w[EMAX];
__device__ float  g_dinv[NMAX];
__device__ __half g_bufY[(size_t)NMAX * 128];   // GEMM out (fp16, gather side)
__device__ float  g_bufH[(size_t)NMAX * 128];   // agg out (fp32, GEMM A side)
// W fragment-interleaved, tf32, transposed: wt[j * NDIM + n] = float2(
//   tf32(W[8*(j>>2)+(j&3)][n]), tf32(W[8*(j>>2)+(j&3)+4][n]) ), j in [0,64)
__device__ float2 g_wt1[64 * 128];
__device__ float2 g_wt2[64 * 128];
__device__ float2 g_wt3[64 * 64];

__device__ __forceinline__ uint32_t f2tf32(float f) {
    uint32_t u;
    asm("cvt.rna.tf32.f32 %0, %1;" : "=r"(u) : "f"(f));
    return u;
}

__device__ __forceinline__ void mma_tf32(float* d, uint32_t a0, uint32_t a1,
                                         uint32_t a2, uint32_t a3,
                                         uint32_t b0, uint32_t b1) {
    asm volatile(
        "mma.sync.aligned.m16n8k8.row.col.f32.tf32.tf32.f32 "
        "{%0,%1,%2,%3}, {%4,%5,%6,%7}, {%8,%9}, {%0,%1,%2,%3};"
        : "+f"(d[0]), "+f"(d[1]), "+f"(d[2]), "+f"(d[3])
        : "r"(a0), "r"(a1), "r"(a2), "r"(a3), "r"(b0), "r"(b1));
}

// ---------------------------------------------------------------- dtype probe
__global__ void detect_dtype_kernel(const void* __restrict__ ei, int E, int N) {
    __shared__ int allok;
    if (threadIdx.x == 0) allok = 1;
    __syncthreads();
    const long long* p = (const long long*)ei;
    int stride = E / 256;
    long long v = p[(size_t)threadIdx.x * stride];
    if (v < 0 || v >= (long long)N) atomicAnd(&allok, 0);
    __syncthreads();
    if (threadIdx.x == 0) g_is64 = allok;
}

__device__ __forceinline__ int edge_at(const void* ei, int E, int half, int e) {
    if (g_is64) return (int)((const long long*)ei)[(size_t)half * E + e];
    return ((const int*)ei)[(size_t)half * E + e];
}

// ---------------------------------------------------------------- CSR build
__global__ void zero_int2_kernel(int n) {
    int i = blockIdx.x * blockDim.x + threadIdx.x;
    if (i < n) { g_deg[i] = 0; g_cnt[i] = 0; }
}
__global__ void count_deg_kernel(const void* __restrict__ ei, int E) {
    int e = blockIdx.x * blockDim.x + threadIdx.x;
    if (e < E) atomicAdd(&g_deg[edge_at(ei, E, 1, e)], 1);
}
__global__ void dinv_kernel(int n) {
    int i = blockIdx.x * blockDim.x + threadIdx.x;
    if (i < n) {
        int d = g_deg[i];
        g_dinv[i] = rsqrtf((float)(d > 0 ? d : 1));
    }
}
// single-block scan: thread-sequential partials + 2-level warp shfl scan
__global__ __launch_bounds__(1024) void scan_kernel(int n) {
    const int tid = threadIdx.x;
    const int lane = tid & 31;
    const int wid = tid >> 5;
    const int C = (n + 1023) / 1024;
    const int base = tid * C;

    int sum = 0;
    for (int i = 0; i < C; i++) {
        int idx = base + i;
        if (idx < n) sum += g_deg[idx];
    }
    // inclusive warp scan
    int inc = sum;
    #pragma unroll
    for (int off = 1; off < 32; off <<= 1) {
        int t = __shfl_up_sync(0xffffffffu, inc, off);
        if (lane >= off) inc += t;
    }
    __shared__ int ws[32];
    if (lane == 31) ws[wid] = inc;
    __syncthreads();
    if (wid == 0) {
        int v = ws[lane];
        #pragma unroll
        for (int off = 1; off < 32; off <<= 1) {
            int t = __shfl_up_sync(0xffffffffu, v, off);
            if (lane >= off) v += t;
        }
        ws[lane] = v;
    }
    __syncthreads();
    int warpoff = (wid == 0) ? 0 : ws[wid - 1];
    int run = warpoff + (inc - sum);   // exclusive prefix for this thread
    if (tid == 0) g_rowstart[0] = 0;
    for (int i = 0; i < C; i++) {
        int idx = base + i;
        if (idx < n) {
            run += g_deg[idx];
            g_rowstart[idx + 1] = run;
        }
    }
}
__global__ void scatter_kernel(const void* __restrict__ ei, int E) {
    int e = blockIdx.x * blockDim.x + threadIdx.x;
    if (e >= E) return;
    int s = edge_at(ei, E, 0, e);
    int d = edge_at(ei, E, 1, e);
    int pos = g_rowstart[d] + atomicAdd(&g_cnt[d], 1);
    g_col[pos] = s;
    g_w[pos] = g_dinv[s] * g_dinv[d];
}

// ---------------------------------------------------------------- W prep
__device__ __forceinline__ float2* wtPtr(int w) {
    return w == 1 ? g_wt1 : (w == 2 ? g_wt2 : g_wt3);
}
template <int WSEL, int NDIM>
__global__ void prep_w(const float* __restrict__ W) {
    int i = blockIdx.x * blockDim.x + threadIdx.x;   // over 64*NDIM
    if (i >= 64 * NDIM) return;
    int j = i / NDIM;
    int n = i % NDIM;
    int k0 = 8 * (j >> 2) + (j & 3);
    float2 v;
    v.x = __uint_as_float(f2tf32(W[(size_t)k0 * NDIM + n]));
    v.y = __uint_as_float(f2tf32(W[(size_t)(k0 + 4) * NDIM + n]));
    wtPtr(WSEL)[i] = v;
}

// ---------------------------------------------------------------- mma GEMM
// Y[M, N_DIM] (fp16) = A[M,128] (fp32) @ W[128,N_DIM].  128 rows/block,
// 8 warps x 16 rows. B staged in SMEM, row stride N_DIM+4 (conflict-free).
template <int N_DIM, int WSEL, bool EXT>
__global__ __launch_bounds__(256) void gemm_mma(const float* __restrict__ Aext, int M) {
    extern __shared__ float2 Bs[];
    constexpr int NT = N_DIM / 8;
    constexpr int NPAD = N_DIM + 4;

    const int tid = threadIdx.x;
    const float2* wt = wtPtr(WSEL);
    #pragma unroll
    for (int l = 0; l < (64 * N_DIM) / 256; l++) {
        int i = tid + l * 256;
        int j = i / N_DIM;
        int n = i % N_DIM;
        Bs[j * NPAD + n] = wt[i];
    }
    __syncthreads();

    const int wid = tid >> 5;
    const int lane = tid & 31;
    const int g = lane >> 2;
    const int tig = lane & 3;
    const int rowBase = blockIdx.x * 128 + wid * 16;
    const int m0 = rowBase + g;
    const int m1 = m0 + 8;
    const float* A = EXT ? Aext : g_bufH;
    const float* Ar0 = A + (size_t)(m0 < M ? m0 : M - 1) * 128;
    const float* Ar1 = A + (size_t)(m1 < M ? m1 : M - 1) * 128;

    float acc[NT][4];
    #pragma unroll
    for (int nt = 0; nt < NT; nt++) {
        acc[nt][0] = 0.f; acc[nt][1] = 0.f; acc[nt][2] = 0.f; acc[nt][3] = 0.f;
    }

    #pragma unroll 4
    for (int s = 0; s < 16; s++) {
        const int k0 = 8 * s;
        uint32_t a0 = f2tf32(Ar0[k0 + tig]);
        uint32_t a2 = f2tf32(Ar0[k0 + tig + 4]);
        uint32_t a1 = f2tf32(Ar1[k0 + tig]);
        uint32_t a3 = f2tf32(Ar1[k0 + tig + 4]);
        const float2* brow = Bs + (size_t)(s * 4 + tig) * NPAD + g;
        #pragma unroll
        for (int nt = 0; nt < NT; nt++) {
            float2 b = brow[nt * 8];
            mma_tf32(acc[nt], a0, a1, a2, a3,
                     __float_as_uint(b.x), __float_as_uint(b.y));
        }
    }

    __half* Y = g_bufY;
    if (m0 < M) {
        __half* dst = Y + (size_t)m0 * N_DIM + tig * 2;
        #pragma unroll
        for (int nt = 0; nt < NT; nt++)
            *(__half2*)(dst + nt * 8) = __float22half2_rn(make_float2(acc[nt][0], acc[nt][1]));
    }
    if (m1 < M) {
        __half* dst = Y + (size_t)m1 * N_DIM + tig * 2;
        #pragma unroll
        for (int nt = 0; nt < NT; nt++)
            *(__half2*)(dst + nt * 8) = __float22half2_rn(make_float2(acc[nt][2], acc[nt][3]));
    }
}

// ---------------------------------------------------------------- SpMM (CSR)
// warp per node; fp16 gather (lane owns 4 cols = 8B/edge), fp32 accum + relu
__global__ __launch_bounds__(256) void agg_relu128_h(int n) {
    const __half* Y = g_bufY;
    float* H = g_bufH;
    int warpId = (blockIdx.x * blockDim.x + threadIdx.x) >> 5;
    int lane = threadIdx.x & 31;
    if (warpId >= n) return;
    int s = g_rowstart[warpId];
    int e = g_rowstart[warpId + 1];
    float4 acc = make_float4(0.f, 0.f, 0.f, 0.f);
    for (int i = s; i < e; i++) {
        int c = g_col[i];
        float ww = g_w[i];
        uint2 raw = __ldg((const uint2*)(Y + (size_t)c * 128) + lane);
        float2 v01 = __half22float2(*(__half2*)&raw.x);
        float2 v23 = __half22float2(*(__half2*)&raw.y);
        acc.x += ww * v01.x;
        acc.y += ww * v01.y;
        acc.z += ww * v23.x;
        acc.w += ww * v23.y;
    }
    acc.x = fmaxf(acc.x, 0.f);
    acc.y = fmaxf(acc.y, 0.f);
    acc.z = fmaxf(acc.z, 0.f);
    acc.w = fmaxf(acc.w, 0.f);
    ((float4*)(H + (size_t)warpId * 128))[lane] = acc;
}

// warp per node, F=64 fp16 (lane owns 2 cols = 4B/edge), relu + softmax
__global__ __launch_bounds__(256) void agg_softmax64_h(float* __restrict__ out, int n) {
    const __half* Y = g_bufY;
    int warpId = (blockIdx.x * blockDim.x + threadIdx.x) >> 5;
    int lane = threadIdx.x & 31;
    if (warpId >= n) return;
    int s = g_rowstart[warpId];
    int e = g_rowstart[warpId + 1];
    float ax = 0.f, ay = 0.f;
    for (int i = s; i < e; i++) {
        int c = g_col[i];
        float ww = g_w[i];
        __half2 h = __ldg((const __half2*)(Y + (size_t)c * 64) + lane);
        float2 v = __half22float2(h);
        ax += ww * v.x;
        ay += ww * v.y;
    }
    ax = fmaxf(ax, 0.f);
    ay = fmaxf(ay, 0.f);
    float m = fmaxf(ax, ay);
    #pragma unroll
    for (int off = 16; off >= 1; off >>= 1)
        m = fmaxf(m, __shfl_xor_sync(0xffffffffu, m, off));
    float e0 = __expf(ax - m);
    float e1 = __expf(ay - m);
    float ssum = e0 + e1;
    #pragma unroll
    for (int off = 16; off >= 1; off >>= 1)
        ssum += __shfl_xor_sync(0xffffffffu, ssum, off);
    float inv = 1.0f / ssum;
    ((float2*)(out + (size_t)warpId * 64))[lane] = make_float2(e0 * inv, e1 * inv);
}

// ---------------------------------------------------------------- launch
extern "C" void kernel_launch(void* const* d_in, const int* in_sizes, int n_in,
                              void* d_out, int out_size) {
    const float* X = (const float*)d_in[0];
    const void* ei = d_in[1];
    const float* W1 = (const float*)d_in[2];
    const float* W2 = (const float*)d_in[3];
    const float* W3 = (const float*)d_in[4];
    float* out = (float*)d_out;

    const int N = in_sizes[0] / 128;   // 50000
    const int E = in_sizes[1] / 2;     // 800000

    const int T = 256;
    detect_dtype_kernel<<<1, 256>>>(ei, E, N);
    zero_int2_kernel<<<(N + T - 1) / T, T>>>(N);
    count_deg_kernel<<<(E + T - 1) / T, T>>>(ei, E);
    dinv_kernel<<<(N + T - 1) / T, T>>>(N);
    scan_kernel<<<1, 1024>>>(N);
    scatter_kernel<<<(E + T - 1) / T, T>>>(ei, E);

    prep_w<1, 128><<<(64 * 128 + T - 1) / T, T>>>(W1);
    prep_w<2, 128><<<(64 * 128 + T - 1) / T, T>>>(W2);
    prep_w<3, 64><<<(64 * 64 + T - 1) / T, T>>>(W3);

    const int gemmBlocks = (N + 127) / 128;
    const int aggBlocks = (N * 32 + T - 1) / T;
    const int SMEM_128 = 64 * (128 + 4) * sizeof(float2);  // 67584
    const int SMEM_64  = 64 * (64 + 4) * sizeof(float2);   // 34816

    auto g1 = gemm_mma<128, 1, true>;
    auto g2 = gemm_mma<128, 2, false>;
    auto g3 = gemm_mma<64, 3, false>;
    cudaFuncSetAttribute(g1, cudaFuncAttributeMaxDynamicSharedMemorySize, SMEM_128);
    cudaFuncSetAttribute(g2, cudaFuncAttributeMaxDynamicSharedMemorySize, SMEM_128);
    cudaFuncSetAttribute(g3, cudaFuncAttributeMaxDynamicSharedMemorySize, SMEM_64);

    // Layer 1: Y = fp16(X @ W1) ; H = relu(agg(Y))
    g1<<<gemmBlocks, 256, SMEM_128>>>(X, N);
    agg_relu128_h<<<aggBlocks, T>>>(N);
    // Layer 2
    g2<<<gemmBlocks, 256, SMEM_128>>>(nullptr, N);
    agg_relu128_h<<<aggBlocks, T>>>(N);
    // Layer 3 (N=64) + fused relu+softmax
    g3<<<gemmBlocks, 256, SMEM_64>>>(nullptr, N);
    agg_softmax64_h<<<aggBlocks, T>>>(out, N);
}

// round 7
// speedup vs baseline: 1.5102x; 1.0071x over previous
#include <cuda_runtime.h>
#include <cuda_fp16.h>
#include <cstdint>

// ---------------------------------------------------------------------------
// GCN: out = softmax(relu(agg(relu(agg(relu(agg(X@W1))@W2))@W3)))
// agg(X) @ W == agg(X @ W)  -> GEMM first (mma.sync tf32), then CSR SpMM.
// GEMM outputs fp16 (gather traffic halved); agg accumulates fp32 with a
// 4x-unrolled, front-batched gather loop (MLP ~4-6 per warp).
// ---------------------------------------------------------------------------

#define NMAX 50000
#define EMAX 800000

__device__ int    g_is64;
__device__ int    g_deg[NMAX];
__device__ int    g_cnt[NMAX];
__device__ int    g_rowstart[NMAX + 1];
__device__ int2   g_cw[EMAX];                   // (col, w-as-bits) per edge
__device__ float  g_dinv[NMAX];
__device__ __half g_bufY[(size_t)NMAX * 128];   // GEMM out (fp16, gather side)
__device__ float  g_bufH[(size_t)NMAX * 128];   // agg out (fp32, GEMM A side)
__device__ float2 g_wt1[64 * 128];
__device__ float2 g_wt2[64 * 128];
__device__ float2 g_wt3[64 * 64];

__device__ __forceinline__ uint32_t f2tf32(float f) {
    uint32_t u;
    asm("cvt.rna.tf32.f32 %0, %1;" : "=r"(u) : "f"(f));
    return u;
}

__device__ __forceinline__ void mma_tf32(float* d, uint32_t a0, uint32_t a1,
                                         uint32_t a2, uint32_t a3,
                                         uint32_t b0, uint32_t b1) {
    asm volatile(
        "mma.sync.aligned.m16n8k8.row.col.f32.tf32.tf32.f32 "
        "{%0,%1,%2,%3}, {%4,%5,%6,%7}, {%8,%9}, {%0,%1,%2,%3};"
        : "+f"(d[0]), "+f"(d[1]), "+f"(d[2]), "+f"(d[3])
        : "r"(a0), "r"(a1), "r"(a2), "r"(a3), "r"(b0), "r"(b1));
}

// ---------------------------------------------------------------- dtype probe
__global__ void detect_dtype_kernel(const void* __restrict__ ei, int E, int N) {
    __shared__ int allok;
    if (threadIdx.x == 0) allok = 1;
    __syncthreads();
    const long long* p = (const long long*)ei;
    int stride = E / 256;
    long long v = p[(size_t)threadIdx.x * stride];
    if (v < 0 || v >= (long long)N) atomicAnd(&allok, 0);
    __syncthreads();
    if (threadIdx.x == 0) g_is64 = allok;
}

__device__ __forceinline__ int edge_at(const void* ei, int E, int half, int e) {
    if (g_is64) return (int)((const long long*)ei)[(size_t)half * E + e];
    return ((const int*)ei)[(size_t)half * E + e];
}

// ---------------------------------------------------------------- CSR build
__global__ void zero_int2_kernel(int n) {
    int i = blockIdx.x * blockDim.x + threadIdx.x;
    if (i < n) { g_deg[i] = 0; g_cnt[i] = 0; }
}
__global__ void count_deg_kernel(const void* __restrict__ ei, int E) {
    int e = blockIdx.x * blockDim.x + threadIdx.x;
    if (e < E) atomicAdd(&g_deg[edge_at(ei, E, 1, e)], 1);
}
__global__ void dinv_kernel(int n) {
    int i = blockIdx.x * blockDim.x + threadIdx.x;
    if (i < n) {
        int d = g_deg[i];
        g_dinv[i] = rsqrtf((float)(d > 0 ? d : 1));
    }
}
// single-block scan: thread-sequential partials + 2-level warp shfl scan
__global__ __launch_bounds__(1024) void scan_kernel(int n) {
    const int tid = threadIdx.x;
    const int lane = tid & 31;
    const int wid = tid >> 5;
    const int C = (n + 1023) / 1024;
    const int base = tid * C;

    int sum = 0;
    for (int i = 0; i < C; i++) {
        int idx = base + i;
        if (idx < n) sum += g_deg[idx];
    }
    int inc = sum;
    #pragma unroll
    for (int off = 1; off < 32; off <<= 1) {
        int t = __shfl_up_sync(0xffffffffu, inc, off);
        if (lane >= off) inc += t;
    }
    __shared__ int ws[32];
    if (lane == 31) ws[wid] = inc;
    __syncthreads();
    if (wid == 0) {
        int v = ws[lane];
        #pragma unroll
        for (int off = 1; off < 32; off <<= 1) {
            int t = __shfl_up_sync(0xffffffffu, v, off);
            if (lane >= off) v += t;
        }
        ws[lane] = v;
    }
    __syncthreads();
    int warpoff = (wid == 0) ? 0 : ws[wid - 1];
    int run = warpoff + (inc - sum);
    if (tid == 0) g_rowstart[0] = 0;
    for (int i = 0; i < C; i++) {
        int idx = base + i;
        if (idx < n) {
            run += g_deg[idx];
            g_rowstart[idx + 1] = run;
        }
    }
}
__global__ void scatter_kernel(const void* __restrict__ ei, int E) {
    int e = blockIdx.x * blockDim.x + threadIdx.x;
    if (e >= E) return;
    int s = edge_at(ei, E, 0, e);
    int d = edge_at(ei, E, 1, e);
    int pos = g_rowstart[d] + atomicAdd(&g_cnt[d], 1);
    g_cw[pos] = make_int2(s, __float_as_int(g_dinv[s] * g_dinv[d]));
}

// ---------------------------------------------------------------- W prep
__device__ __forceinline__ float2* wtPtr(int w) {
    return w == 1 ? g_wt1 : (w == 2 ? g_wt2 : g_wt3);
}
template <int WSEL, int NDIM>
__global__ void prep_w(const float* __restrict__ W) {
    int i = blockIdx.x * blockDim.x + threadIdx.x;
    if (i >= 64 * NDIM) return;
    int j = i / NDIM;
    int n = i % NDIM;
    int k0 = 8 * (j >> 2) + (j & 3);
    float2 v;
    v.x = __uint_as_float(f2tf32(W[(size_t)k0 * NDIM + n]));
    v.y = __uint_as_float(f2tf32(W[(size_t)(k0 + 4) * NDIM + n]));
    wtPtr(WSEL)[i] = v;
}

// ---------------------------------------------------------------- mma GEMM
template <int N_DIM, int WSEL, bool EXT>
__global__ __launch_bounds__(256) void gemm_mma(const float* __restrict__ Aext, int M) {
    extern __shared__ float2 Bs[];
    constexpr int NT = N_DIM / 8;
    constexpr int NPAD = N_DIM + 4;

    const int tid = threadIdx.x;
    const float2* wt = wtPtr(WSEL);
    #pragma unroll
    for (int l = 0; l < (64 * N_DIM) / 256; l++) {
        int i = tid + l * 256;
        int j = i / N_DIM;
        int n = i % N_DIM;
        Bs[j * NPAD + n] = wt[i];
    }
    __syncthreads();

    const int wid = tid >> 5;
    const int lane = tid & 31;
    const int g = lane >> 2;
    const int tig = lane & 3;
    const int rowBase = blockIdx.x * 128 + wid * 16;
    const int m0 = rowBase + g;
    const int m1 = m0 + 8;
    const float* A = EXT ? Aext : g_bufH;
    const float* Ar0 = A + (size_t)(m0 < M ? m0 : M - 1) * 128;
    const float* Ar1 = A + (size_t)(m1 < M ? m1 : M - 1) * 128;

    float acc[NT][4];
    #pragma unroll
    for (int nt = 0; nt < NT; nt++) {
        acc[nt][0] = 0.f; acc[nt][1] = 0.f; acc[nt][2] = 0.f; acc[nt][3] = 0.f;
    }

    #pragma unroll 4
    for (int s = 0; s < 16; s++) {
        const int k0 = 8 * s;
        uint32_t a0 = f2tf32(Ar0[k0 + tig]);
        uint32_t a2 = f2tf32(Ar0[k0 + tig + 4]);
        uint32_t a1 = f2tf32(Ar1[k0 + tig]);
        uint32_t a3 = f2tf32(Ar1[k0 + tig + 4]);
        const float2* brow = Bs + (size_t)(s * 4 + tig) * NPAD + g;
        #pragma unroll
        for (int nt = 0; nt < NT; nt++) {
            float2 b = brow[nt * 8];
            mma_tf32(acc[nt], a0, a1, a2, a3,
                     __float_as_uint(b.x), __float_as_uint(b.y));
        }
    }

    __half* Y = g_bufY;
    if (m0 < M) {
        __half* dst = Y + (size_t)m0 * N_DIM + tig * 2;
        #pragma unroll
        for (int nt = 0; nt < NT; nt++)
            *(__half2*)(dst + nt * 8) = __float22half2_rn(make_float2(acc[nt][0], acc[nt][1]));
    }
    if (m1 < M) {
        __half* dst = Y + (size_t)m1 * N_DIM + tig * 2;
        #pragma unroll
        for (int nt = 0; nt < NT; nt++)
            *(__half2*)(dst + nt * 8) = __float22half2_rn(make_float2(acc[nt][2], acc[nt][3]));
    }
}

// ---------------------------------------------------------------- SpMM (CSR)
// warp per node; fp16 gather, 4x unroll with front-batched loads (MLP~4-6)
__global__ __launch_bounds__(256) void agg_relu128_h(int n) {
    const __half* Y = g_bufY;
    float* H = g_bufH;
    int warpId = (blockIdx.x * blockDim.x + threadIdx.x) >> 5;
    int lane = threadIdx.x & 31;
    if (warpId >= n) return;
    int s = g_rowstart[warpId];
    int e = g_rowstart[warpId + 1];
    float4 acc = make_float4(0.f, 0.f, 0.f, 0.f);

    int i = s;
    for (; i + 4 <= e; i += 4) {
        int2 p0 = __ldg(g_cw + i + 0);
        int2 p1 = __ldg(g_cw + i + 1);
        int2 p2 = __ldg(g_cw + i + 2);
        int2 p3 = __ldg(g_cw + i + 3);
        uint2 r0 = __ldg((const uint2*)(Y + (size_t)p0.x * 128) + lane);
        uint2 r1 = __ldg((const uint2*)(Y + (size_t)p1.x * 128) + lane);
        uint2 r2 = __ldg((const uint2*)(Y + (size_t)p2.x * 128) + lane);
        uint2 r3 = __ldg((const uint2*)(Y + (size_t)p3.x * 128) + lane);
        float w0 = __int_as_float(p0.y), w1 = __int_as_float(p1.y);
        float w2 = __int_as_float(p2.y), w3 = __int_as_float(p3.y);
        float2 a, b;
        a = __half22float2(*(__half2*)&r0.x); b = __half22float2(*(__half2*)&r0.y);
        acc.x += w0 * a.x; acc.y += w0 * a.y; acc.z += w0 * b.x; acc.w += w0 * b.y;
        a = __half22float2(*(__half2*)&r1.x); b = __half22float2(*(__half2*)&r1.y);
        acc.x += w1 * a.x; acc.y += w1 * a.y; acc.z += w1 * b.x; acc.w += w1 * b.y;
        a = __half22float2(*(__half2*)&r2.x); b = __half22float2(*(__half2*)&r2.y);
        acc.x += w2 * a.x; acc.y += w2 * a.y; acc.z += w2 * b.x; acc.w += w2 * b.y;
        a = __half22float2(*(__half2*)&r3.x); b = __half22float2(*(__half2*)&r3.y);
        acc.x += w3 * a.x; acc.y += w3 * a.y; acc.z += w3 * b.x; acc.w += w3 * b.y;
    }
    for (; i < e; i++) {
        int2 p = __ldg(g_cw + i);
        float ww = __int_as_float(p.y);
        uint2 r = __ldg((const uint2*)(Y + (size_t)p.x * 128) + lane);
        float2 a = __half22float2(*(__half2*)&r.x);
        float2 b = __half22float2(*(__half2*)&r.y);
        acc.x += ww * a.x; acc.y += ww * a.y; acc.z += ww * b.x; acc.w += ww * b.y;
    }
    acc.x = fmaxf(acc.x, 0.f);
    acc.y = fmaxf(acc.y, 0.f);
    acc.z = fmaxf(acc.z, 0.f);
    acc.w = fmaxf(acc.w, 0.f);
    ((float4*)(H + (size_t)warpId * 128))[lane] = acc;
}

// warp per node, F=64 fp16, 4x unroll, relu + softmax
__global__ __launch_bounds__(256) void agg_softmax64_h(float* __restrict__ out, int n) {
    const __half* Y = g_bufY;
    int warpId = (blockIdx.x * blockDim.x + threadIdx.x) >> 5;
    int lane = threadIdx.x & 31;
    if (warpId >= n) return;
    int s = g_rowstart[warpId];
    int e = g_rowstart[warpId + 1];
    float ax = 0.f, ay = 0.f;

    int i = s;
    for (; i + 4 <= e; i += 4) {
        int2 p0 = __ldg(g_cw + i + 0);
        int2 p1 = __ldg(g_cw + i + 1);
        int2 p2 = __ldg(g_cw + i + 2);
        int2 p3 = __ldg(g_cw + i + 3);
        __half2 h0 = __ldg((const __half2*)(Y + (size_t)p0.x * 64) + lane);
        __half2 h1 = __ldg((const __half2*)(Y + (size_t)p1.x * 64) + lane);
        __half2 h2 = __ldg((const __half2*)(Y + (size_t)p2.x * 64) + lane);
        __half2 h3 = __ldg((const __half2*)(Y + (size_t)p3.x * 64) + lane);
        float w0 = __int_as_float(p0.y), w1 = __int_as_float(p1.y);
        float w2 = __int_as_float(p2.y), w3 = __int_as_float(p3.y);
        float2 v;
        v = __half22float2(h0); ax += w0 * v.x; ay += w0 * v.y;
        v = __half22float2(h1); ax += w1 * v.x; ay += w1 * v.y;
        v = __half22float2(h2); ax += w2 * v.x; ay += w2 * v.y;
        v = __half22float2(h3); ax += w3 * v.x; ay += w3 * v.y;
    }
    for (; i < e; i++) {
        int2 p = __ldg(g_cw + i);
        float ww = __int_as_float(p.y);
        float2 v = __half22float2(__ldg((const __half2*)(Y + (size_t)p.x * 64) + lane));
        ax += ww * v.x; ay += ww * v.y;
    }
    ax = fmaxf(ax, 0.f);
    ay = fmaxf(ay, 0.f);
    float m = fmaxf(ax, ay);
    #pragma unroll
    for (int off = 16; off >= 1; off >>= 1)
        m = fmaxf(m, __shfl_xor_sync(0xffffffffu, m, off));
    float e0 = __expf(ax - m);
    float e1 = __expf(ay - m);
    float ssum = e0 + e1;
    #pragma unroll
    for (int off = 16; off >= 1; off >>= 1)
        ssum += __shfl_xor_sync(0xffffffffu, ssum, off);
    float inv = 1.0f / ssum;
    ((float2*)(out + (size_t)warpId * 64))[lane] = make_float2(e0 * inv, e1 * inv);
}

// ---------------------------------------------------------------- launch
extern "C" void kernel_launch(void* const* d_in, const int* in_sizes, int n_in,
                              void* d_out, int out_size) {
    const float* X = (const float*)d_in[0];
    const void* ei = d_in[1];
    const float* W1 = (const float*)d_in[2];
    const float* W2 = (const float*)d_in[3];
    const float* W3 = (const float*)d_in[4];
    float* out = (float*)d_out;

    const int N = in_sizes[0] / 128;   // 50000
    const int E = in_sizes[1] / 2;     // 800000

    const int T = 256;
    detect_dtype_kernel<<<1, 256>>>(ei, E, N);
    zero_int2_kernel<<<(N + T - 1) / T, T>>>(N);
    count_deg_kernel<<<(E + T - 1) / T, T>>>(ei, E);
    dinv_kernel<<<(N + T - 1) / T, T>>>(N);
    scan_kernel<<<1, 1024>>>(N);
    scatter_kernel<<<(E + T - 1) / T, T>>>(ei, E);

    prep_w<1, 128><<<(64 * 128 + T - 1) / T, T>>>(W1);
    prep_w<2, 128><<<(64 * 128 + T - 1) / T, T>>>(W2);
    prep_w<3, 64><<<(64 * 64 + T - 1) / T, T>>>(W3);

    const int gemmBlocks = (N + 127) / 128;
    const int aggBlocks = (N * 32 + T - 1) / T;
    const int SMEM_128 = 64 * (128 + 4) * sizeof(float2);  // 67584
    const int SMEM_64  = 64 * (64 + 4) * sizeof(float2);   // 34816

    auto g1 = gemm_mma<128, 1, true>;
    auto g2 = gemm_mma<128, 2, false>;
    auto g3 = gemm_mma<64, 3, false>;
    cudaFuncSetAttribute(g1, cudaFuncAttributeMaxDynamicSharedMemorySize, SMEM_128);
    cudaFuncSetAttribute(g2, cudaFuncAttributeMaxDynamicSharedMemorySize, SMEM_128);
    cudaFuncSetAttribute(g3, cudaFuncAttributeMaxDynamicSharedMemorySize, SMEM_64);

    // Layer 1: Y = fp16(X @ W1) ; H = relu(agg(Y))
    g1<<<gemmBlocks, 256, SMEM_128>>>(X, N);
    agg_relu128_h<<<aggBlocks, T>>>(N);
    // Layer 2
    g2<<<gemmBlocks, 256, SMEM_128>>>(nullptr, N);
    agg_relu128_h<<<aggBlocks, T>>>(N);
    // Layer 3 (N=64) + fused relu+softmax
    g3<<<gemmBlocks, 256, SMEM_64>>>(nullptr, N);
    agg_softmax64_h<<<aggBlocks, T>>>(out, N);
}